// round 1
// baseline (speedup 1.0000x reference)
#include <cuda_runtime.h>

// GAT over 16384 independent 32-node cliques, fully fused: one CTA per graph.
// 128 threads/CTA: warp = head for attention phases, thread = out-channel for GEMMs.

#define NCOL 32
#define HEADS 4
#define FH 128          // H * HID
#define F3 24           // H * OUT
#define THREADS 128
#define NEG_SLOPE 0.2f

__device__ __forceinline__ float lrelu(float x) { return x > 0.f ? x : NEG_SLOPE * x; }

// Attention for one layer. h[n][head*D+d] in smem (stride FH), writes hout (stride FH).
// Warp w handles head w; lane = node index. All h reads are warp-uniform broadcasts.
template <int D>
__device__ __forceinline__ void gat_attention(
    const float (*__restrict__ h)[FH], float (*__restrict__ hout)[FH],
    const float* __restrict__ a_src, const float* __restrict__ a_dst,
    const float* __restrict__ bias,
    float* __restrict__ s_src, float* __restrict__ s_dst, int t)
{
    const int head = t >> 5;   // warp id
    const int n = t & 31;      // lane id

    // per-(node, head) source/target scores
    float ss = 0.f, sd = 0.f;
#pragma unroll
    for (int d = 0; d < D; d++) {
        float hv = h[n][head * D + d];
        ss += hv * a_src[head * D + d];
        sd += hv * a_dst[head * D + d];
    }
    s_src[head * NCOL + n] = ss;
    s_dst[head * NCOL + n] = sd;
    __syncthreads();

    // lane n is target node i: softmax over sources j, then aggregate
    const float sdst = s_dst[head * NCOL + n];
    float e[NCOL];
    float m = -1e30f;
#pragma unroll
    for (int j = 0; j < NCOL; j++) {
        float v = lrelu(sdst + s_src[head * NCOL + j]);
        e[j] = v;
        m = fmaxf(m, v);
    }
    float sum = 0.f;
#pragma unroll
    for (int j = 0; j < NCOL; j++) {
        e[j] = __expf(e[j] - m);
        sum += e[j];
    }
    const float rinv = 1.f / sum;

#pragma unroll
    for (int d = 0; d < D; d++) {
        float acc = 0.f;
#pragma unroll
        for (int j = 0; j < NCOL; j++)
            acc += e[j] * h[j][head * D + d];   // warp-uniform broadcast
        hout[n][head * D + d] = acc * rinv + bias[head * D + d];
    }
    __syncthreads();
}

__global__ void __launch_bounds__(THREADS) gat_fused_kernel(
    const float* __restrict__ xs,       // [B, R, 32]
    const float* __restrict__ pe,       // [B, 32, 15]
    const float* __restrict__ W1,       // [16, 128]
    const float* __restrict__ as1, const float* __restrict__ ad1,  // [4,32]
    const float* __restrict__ b1,       // [128]
    const float* __restrict__ W2,       // [128, 128]
    const float* __restrict__ as2, const float* __restrict__ ad2,
    const float* __restrict__ b2,
    const float* __restrict__ W3,       // [128, 24]
    const float* __restrict__ as3, const float* __restrict__ ad3,  // [4,6]
    const float* __restrict__ b3,       // [24]
    const float* __restrict__ lw,       // [24, 64]
    const float* __restrict__ lb,       // [64]
    float* __restrict__ out,            // [B*R, 64]
    int R)
{
    __shared__ float hA[NCOL][FH];
    __shared__ float hB[NCOL][FH];
    __shared__ float s_src[HEADS * NCOL];
    __shared__ float s_dst[HEADS * NCOL];
    __shared__ float xin[NCOL][16];
    __shared__ float cs[F3];

    const int g = blockIdx.x;
    const int b = g / R;
    const int r = g - b * R;
    const int t = threadIdx.x;

    // ---- build input features: x[n] = [xs[b,r,n], pe[b,n,0..14]] ----
    for (int idx = t; idx < NCOL * 16; idx += THREADS) {
        int n = idx >> 4, f = idx & 15;
        float v;
        if (f == 0) v = xs[(size_t)(b * R + r) * NCOL + n];
        else        v = pe[(b * NCOL + n) * 15 + (f - 1)];
        xin[n][f] = v;
    }
    __syncthreads();

    // ---- layer 1 GEMM: hA[n][t] = sum_f xin[n][f] * W1[f][t] ----
    {
        float w[16];
#pragma unroll
        for (int f = 0; f < 16; f++) w[f] = W1[f * FH + t];
        for (int n = 0; n < NCOL; n++) {
            float acc = 0.f;
#pragma unroll
            for (int f = 0; f < 16; f++) acc += xin[n][f] * w[f];
            hA[n][t] = acc;
        }
    }
    __syncthreads();
    gat_attention<32>(hA, hB, as1, ad1, b1, s_src, s_dst, t);

    // ---- layer 2 GEMM: hA[n][t] = sum_f hB[n][f] * W2[f][t] (8-node blocking) ----
    for (int n0 = 0; n0 < NCOL; n0 += 8) {
        float acc[8];
#pragma unroll
        for (int nn = 0; nn < 8; nn++) acc[nn] = 0.f;
#pragma unroll 4
        for (int f = 0; f < FH; f++) {
            float w = W2[f * FH + t];
#pragma unroll
            for (int nn = 0; nn < 8; nn++) acc[nn] += hB[n0 + nn][f] * w;
        }
#pragma unroll
        for (int nn = 0; nn < 8; nn++) hA[n0 + nn][t] = acc[nn];
    }
    __syncthreads();
    gat_attention<32>(hA, hB, as2, ad2, b2, s_src, s_dst, t);

    // ---- layer 3 GEMM: 32x24 outputs, 6 (n,j) pairs per thread ----
#pragma unroll
    for (int k = 0; k < 6; k++) {
        int p = t + k * THREADS;       // 0..767
        int n = p / F3;
        int j = p - n * F3;
        float acc = 0.f;
#pragma unroll 4
        for (int f = 0; f < FH; f++) acc += hB[n][f] * W3[f * F3 + j];
        hA[n][j] = acc;
    }
    __syncthreads();
    gat_attention<6>(hA, hB, as3, ad3, b3, s_src, s_dst, t);

    // ---- final: mean over nodes commutes with linear ----
    if (t < F3) {
        float s = 0.f;
#pragma unroll
        for (int n = 0; n < NCOL; n++) s += hB[n][t];
        cs[t] = s * (1.f / 32.f);
    }
    __syncthreads();
    if (t < 64) {
        float acc = lb[t];
#pragma unroll
        for (int k = 0; k < F3; k++) acc += cs[k] * lw[k * 64 + t];
        out[(size_t)g * 64 + t] = acc;
    }
}

extern "C" void kernel_launch(void* const* d_in, const int* in_sizes, int n_in,
                              void* d_out, int out_size)
{
    const float* xs  = (const float*)d_in[0];
    const float* pe  = (const float*)d_in[1];
    const float* W1  = (const float*)d_in[2];
    const float* as1 = (const float*)d_in[3];
    const float* ad1 = (const float*)d_in[4];
    const float* b1  = (const float*)d_in[5];
    const float* W2  = (const float*)d_in[6];
    const float* as2 = (const float*)d_in[7];
    const float* ad2 = (const float*)d_in[8];
    const float* b2  = (const float*)d_in[9];
    const float* W3  = (const float*)d_in[10];
    const float* as3 = (const float*)d_in[11];
    const float* ad3 = (const float*)d_in[12];
    const float* b3  = (const float*)d_in[13];
    const float* lw  = (const float*)d_in[14];
    const float* lb  = (const float*)d_in[15];
    float* out = (float*)d_out;

    // derive shapes: in_sizes[1] = B*32*15, in_sizes[0] = B*R*32
    int B = in_sizes[1] / (32 * 15);
    int R = in_sizes[0] / (B * 32);
    int G = B * R;

    gat_fused_kernel<<<G, THREADS>>>(xs, pe, W1, as1, ad1, b1,
                                     W2, as2, ad2, b2,
                                     W3, as3, ad3, b3,
                                     lw, lb, out, R);
}

// round 2
// speedup vs baseline: 1.7923x; 1.7923x over previous
#include <cuda_runtime.h>

// GAT over 16384 independent 32-node cliques, fully fused: one CTA per graph.
// 128 threads/CTA: warp = head for attention, thread = out-channel for GEMMs.
// All shared-memory h tiles padded to 132 floats/row (16B aligned, conflict-free
// for lane-strided float4 access) and accessed via float4 to cut LDS issue 4x.

#define NCOL 32
#define HEADS 4
#define FH 128          // H * HID
#define FHP 132         // padded row (floats); 528B stride -> conflict-free f4
#define F3 24           // H * OUT
#define THREADS 128
#define NEG_SLOPE 0.2f

__device__ __forceinline__ float lrelu(float x) { return x > 0.f ? x : NEG_SLOPE * x; }

// Attention for D=32 heads (layers 1 & 2), fully float4.
__device__ __forceinline__ void gat_attention32(
    const float (*__restrict__ h)[FHP], float (*__restrict__ hout)[FHP],
    const float* __restrict__ a_src, const float* __restrict__ a_dst,
    const float* __restrict__ bias,
    float* __restrict__ s_src, float* __restrict__ s_dst, int t)
{
    const int head = t >> 5;
    const int n = t & 31;
    const int c0 = head * 32;

    // phase 1: per-(node, head) scores — lane-strided float4, conflict-free
    float ss = 0.f, sd = 0.f;
#pragma unroll
    for (int q = 0; q < 8; q++) {
        float4 hv  = *(const float4*)&h[n][c0 + 4 * q];
        float4 as4 = ((const float4*)(a_src + c0))[q];
        float4 ad4 = ((const float4*)(a_dst + c0))[q];
        ss = fmaf(hv.x, as4.x, fmaf(hv.y, as4.y, fmaf(hv.z, as4.z, fmaf(hv.w, as4.w, ss))));
        sd = fmaf(hv.x, ad4.x, fmaf(hv.y, ad4.y, fmaf(hv.z, ad4.z, fmaf(hv.w, ad4.w, sd))));
    }
    s_src[head * NCOL + n] = ss;
    s_dst[head * NCOL + n] = sd;
    __syncthreads();

    // lane n = target node i: softmax over sources j
    const float sdst = s_dst[head * NCOL + n];
    float e[NCOL];
    float m = -1e30f;
#pragma unroll
    for (int j = 0; j < NCOL; j++) {
        float v = lrelu(sdst + s_src[head * NCOL + j]);
        e[j] = v;
        m = fmaxf(m, v);
    }
    float sum = 0.f;
#pragma unroll
    for (int j = 0; j < NCOL; j++) {
        e[j] = __expf(e[j] - m);
        sum += e[j];
    }
    const float rinv = 1.f / sum;

    // aggregate: broadcast float4 reads of h rows
#pragma unroll
    for (int q = 0; q < 8; q++) {
        float ax = 0.f, ay = 0.f, az = 0.f, aw = 0.f;
#pragma unroll
        for (int j = 0; j < NCOL; j++) {
            float4 hv = *(const float4*)&h[j][c0 + 4 * q];
            ax = fmaf(e[j], hv.x, ax);
            ay = fmaf(e[j], hv.y, ay);
            az = fmaf(e[j], hv.z, az);
            aw = fmaf(e[j], hv.w, aw);
        }
        float4 b4 = ((const float4*)(bias + c0))[q];
        float4 o;
        o.x = fmaf(ax, rinv, b4.x);
        o.y = fmaf(ay, rinv, b4.y);
        o.z = fmaf(az, rinv, b4.z);
        o.w = fmaf(aw, rinv, b4.w);
        *(float4*)&hout[n][c0 + 4 * q] = o;
    }
    __syncthreads();
}

// Attention for D=6 (layer 3) — small, scalar.
__device__ __forceinline__ void gat_attention6(
    const float (*__restrict__ h)[FHP], float (*__restrict__ hout)[FHP],
    const float* __restrict__ a_src, const float* __restrict__ a_dst,
    const float* __restrict__ bias,
    float* __restrict__ s_src, float* __restrict__ s_dst, int t)
{
    const int head = t >> 5;
    const int n = t & 31;
    const int c0 = head * 6;

    float ss = 0.f, sd = 0.f;
#pragma unroll
    for (int d = 0; d < 6; d++) {
        float hv = h[n][c0 + d];
        ss = fmaf(hv, a_src[c0 + d], ss);
        sd = fmaf(hv, a_dst[c0 + d], sd);
    }
    s_src[head * NCOL + n] = ss;
    s_dst[head * NCOL + n] = sd;
    __syncthreads();

    const float sdst = s_dst[head * NCOL + n];
    float e[NCOL];
    float m = -1e30f;
#pragma unroll
    for (int j = 0; j < NCOL; j++) {
        float v = lrelu(sdst + s_src[head * NCOL + j]);
        e[j] = v;
        m = fmaxf(m, v);
    }
    float sum = 0.f;
#pragma unroll
    for (int j = 0; j < NCOL; j++) {
        e[j] = __expf(e[j] - m);
        sum += e[j];
    }
    const float rinv = 1.f / sum;

#pragma unroll
    for (int d = 0; d < 6; d++) {
        float acc = 0.f;
#pragma unroll
        for (int j = 0; j < NCOL; j++)
            acc = fmaf(e[j], h[j][c0 + d], acc);
        hout[n][c0 + d] = fmaf(acc, rinv, bias[c0 + d]);
    }
    __syncthreads();
}

__global__ void __launch_bounds__(THREADS, 6) gat_fused_kernel(
    const float* __restrict__ xs,       // [B, R, 32]
    const float* __restrict__ pe,       // [B, 32, 15]
    const float* __restrict__ W1,       // [16, 128]
    const float* __restrict__ as1, const float* __restrict__ ad1,
    const float* __restrict__ b1,
    const float* __restrict__ W2,       // [128, 128]
    const float* __restrict__ as2, const float* __restrict__ ad2,
    const float* __restrict__ b2,
    const float* __restrict__ W3,       // [128, 24]
    const float* __restrict__ as3, const float* __restrict__ ad3,
    const float* __restrict__ b3,
    const float* __restrict__ lw,       // [24, 64]
    const float* __restrict__ lb,       // [64]
    float* __restrict__ out,            // [B*R, 64]
    int R)
{
    __shared__ float hA[NCOL][FHP];
    __shared__ float hB[NCOL][FHP];
    __shared__ float s_src[HEADS * NCOL];
    __shared__ float s_dst[HEADS * NCOL];
    __shared__ float xin[NCOL][16];
    __shared__ float cs[F3];

    const int g = blockIdx.x;
    const int b = g / R;
    const int r = g - b * R;
    const int t = threadIdx.x;

    // ---- build input features: x[n] = [xs[b,r,n], pe[b,n,0..14]] ----
    for (int idx = t; idx < NCOL * 16; idx += THREADS) {
        int n = idx >> 4, f = idx & 15;
        float v;
        if (f == 0) v = xs[(size_t)(b * R + r) * NCOL + n];
        else        v = pe[(b * NCOL + n) * 15 + (f - 1)];
        xin[n][f] = v;
    }
    __syncthreads();

    // ---- layer 1 GEMM: hA[n][t] = sum_f xin[n][f] * W1[f][t] ----
    {
        float w[16];
#pragma unroll
        for (int f = 0; f < 16; f++) w[f] = W1[f * FH + t];
#pragma unroll 4
        for (int n = 0; n < NCOL; n++) {
            const float4* xr = (const float4*)&xin[n][0];
            float acc = 0.f;
#pragma unroll
            for (int q = 0; q < 4; q++) {
                float4 xv = xr[q];
                acc = fmaf(xv.x, w[4*q+0], acc);
                acc = fmaf(xv.y, w[4*q+1], acc);
                acc = fmaf(xv.z, w[4*q+2], acc);
                acc = fmaf(xv.w, w[4*q+3], acc);
            }
            hA[n][t] = acc;
        }
    }
    __syncthreads();
    gat_attention32(hA, hB, as1, ad1, b1, s_src, s_dst, t);

    // ---- layer 2 GEMM: hA[n][t] = sum_f hB[n][f] * W2[f][t] ----
    // 16-node register blocking x2 passes; float4 h reads (broadcast LDS.128).
#pragma unroll
    for (int half = 0; half < 2; half++) {
        float acc[16];
#pragma unroll
        for (int nn = 0; nn < 16; nn++) acc[nn] = 0.f;
#pragma unroll 2
        for (int f0 = 0; f0 < FH; f0 += 4) {
            float4 w;
            w.x = W2[(f0 + 0) * FH + t];
            w.y = W2[(f0 + 1) * FH + t];
            w.z = W2[(f0 + 2) * FH + t];
            w.w = W2[(f0 + 3) * FH + t];
#pragma unroll
            for (int nn = 0; nn < 16; nn++) {
                float4 hv = *(const float4*)&hB[half * 16 + nn][f0];
                acc[nn] = fmaf(hv.x, w.x, acc[nn]);
                acc[nn] = fmaf(hv.y, w.y, acc[nn]);
                acc[nn] = fmaf(hv.z, w.z, acc[nn]);
                acc[nn] = fmaf(hv.w, w.w, acc[nn]);
            }
        }
#pragma unroll
        for (int nn = 0; nn < 16; nn++) hA[half * 16 + nn][t] = acc[nn];
    }
    __syncthreads();
    gat_attention32(hA, hB, as2, ad2, b2, s_src, s_dst, t);

    // ---- layer 3 GEMM: 32x24 outputs, 6 (n,j) pairs per thread ----
#pragma unroll
    for (int k = 0; k < 6; k++) {
        int p = t + k * THREADS;       // 0..767
        int n = p / F3;
        int j = p - n * F3;
        float acc = 0.f;
#pragma unroll 4
        for (int f0 = 0; f0 < FH; f0 += 4) {
            float4 hv = *(const float4*)&hB[n][f0];
            acc = fmaf(hv.x, W3[(f0 + 0) * F3 + j], acc);
            acc = fmaf(hv.y, W3[(f0 + 1) * F3 + j], acc);
            acc = fmaf(hv.z, W3[(f0 + 2) * F3 + j], acc);
            acc = fmaf(hv.w, W3[(f0 + 3) * F3 + j], acc);
        }
        hA[n][j] = acc;
    }
    __syncthreads();
    gat_attention6(hA, hB, as3, ad3, b3, s_src, s_dst, t);

    // ---- final: mean over nodes commutes with linear ----
    if (t < F3) {
        float s = 0.f;
#pragma unroll
        for (int n = 0; n < NCOL; n++) s += hB[n][t];
        cs[t] = s * (1.f / 32.f);
    }
    __syncthreads();
    if (t < 64) {
        float acc = lb[t];
#pragma unroll
        for (int k = 0; k < F3; k++) acc = fmaf(cs[k], lw[k * 64 + t], acc);
        out[(size_t)g * 64 + t] = acc;
    }
}

extern "C" void kernel_launch(void* const* d_in, const int* in_sizes, int n_in,
                              void* d_out, int out_size)
{
    const float* xs  = (const float*)d_in[0];
    const float* pe  = (const float*)d_in[1];
    const float* W1  = (const float*)d_in[2];
    const float* as1 = (const float*)d_in[3];
    const float* ad1 = (const float*)d_in[4];
    const float* b1  = (const float*)d_in[5];
    const float* W2  = (const float*)d_in[6];
    const float* as2 = (const float*)d_in[7];
    const float* ad2 = (const float*)d_in[8];
    const float* b2  = (const float*)d_in[9];
    const float* W3  = (const float*)d_in[10];
    const float* as3 = (const float*)d_in[11];
    const float* ad3 = (const float*)d_in[12];
    const float* b3  = (const float*)d_in[13];
    const float* lw  = (const float*)d_in[14];
    const float* lb  = (const float*)d_in[15];
    float* out = (float*)d_out;

    int B = in_sizes[1] / (32 * 15);
    int R = in_sizes[0] / (B * 32);
    int G = B * R;

    gat_fused_kernel<<<G, THREADS>>>(xs, pe, W1, as1, ad1, b1,
                                     W2, as2, ad2, b2,
                                     W3, as3, ad3, b3,
                                     lw, lb, out, R);
}

// round 3
// speedup vs baseline: 2.3713x; 1.3231x over previous
#include <cuda_runtime.h>

// GAT over 16384 independent 32-node cliques, fully fused: one CTA per graph.
// GEMMs use 2-D register tiles (8 nodes x 4 channels) so each LDS.128/LDG.128
// feeds many FFMAs; attention warps map to heads with broadcast smem reads.

#define NCOL 32
#define HEADS 4
#define FH 128          // H * HID
#define FHP 132         // padded row (floats)
#define F3 24           // H * OUT
#define THREADS 128
#define NEG_SLOPE 0.2f

__device__ __forceinline__ float lrelu(float x) { return x > 0.f ? x : NEG_SLOPE * x; }

// Attention for D=32 heads (layers 1 & 2), float4 everywhere.
__device__ __forceinline__ void gat_attention32(
    const float (*__restrict__ h)[FHP], float (*__restrict__ hout)[FHP],
    const float* __restrict__ a_src, const float* __restrict__ a_dst,
    const float* __restrict__ bias,
    float* __restrict__ s_src, float* __restrict__ s_dst, int t)
{
    const int head = t >> 5;
    const int n = t & 31;
    const int c0 = head * 32;

    float ss = 0.f, sd = 0.f;
#pragma unroll
    for (int q = 0; q < 8; q++) {
        float4 hv  = *(const float4*)&h[n][c0 + 4 * q];
        float4 as4 = ((const float4*)(a_src + c0))[q];
        float4 ad4 = ((const float4*)(a_dst + c0))[q];
        ss = fmaf(hv.x, as4.x, fmaf(hv.y, as4.y, fmaf(hv.z, as4.z, fmaf(hv.w, as4.w, ss))));
        sd = fmaf(hv.x, ad4.x, fmaf(hv.y, ad4.y, fmaf(hv.z, ad4.z, fmaf(hv.w, ad4.w, sd))));
    }
    s_src[head * NCOL + n] = ss;
    s_dst[head * NCOL + n] = sd;
    __syncthreads();

    const float sdst = s_dst[head * NCOL + n];
    float e[NCOL];
    float m = -1e30f;
#pragma unroll
    for (int j = 0; j < NCOL; j++) {
        float v = lrelu(sdst + s_src[head * NCOL + j]);
        e[j] = v;
        m = fmaxf(m, v);
    }
    float sum = 0.f;
#pragma unroll
    for (int j = 0; j < NCOL; j++) {
        e[j] = __expf(e[j] - m);
        sum += e[j];
    }
    const float rinv = 1.f / sum;

#pragma unroll
    for (int q = 0; q < 8; q++) {
        float ax = 0.f, ay = 0.f, az = 0.f, aw = 0.f;
#pragma unroll
        for (int j = 0; j < NCOL; j++) {
            float4 hv = *(const float4*)&h[j][c0 + 4 * q];   // broadcast
            ax = fmaf(e[j], hv.x, ax);
            ay = fmaf(e[j], hv.y, ay);
            az = fmaf(e[j], hv.z, az);
            aw = fmaf(e[j], hv.w, aw);
        }
        float4 b4 = ((const float4*)(bias + c0))[q];
        float4 o;
        o.x = fmaf(ax, rinv, b4.x);
        o.y = fmaf(ay, rinv, b4.y);
        o.z = fmaf(az, rinv, b4.z);
        o.w = fmaf(aw, rinv, b4.w);
        *(float4*)&hout[n][c0 + 4 * q] = o;
    }
    __syncthreads();
}

// Attention for D=6 (layer 3): float2 loads.
__device__ __forceinline__ void gat_attention6(
    const float (*__restrict__ h)[FHP], float (*__restrict__ hout)[FHP],
    const float* __restrict__ a_src, const float* __restrict__ a_dst,
    const float* __restrict__ bias,
    float* __restrict__ s_src, float* __restrict__ s_dst, int t)
{
    const int head = t >> 5;
    const int n = t & 31;
    const int c0 = head * 6;

    float ss = 0.f, sd = 0.f;
#pragma unroll
    for (int q = 0; q < 3; q++) {
        float2 hv = *(const float2*)&h[n][c0 + 2 * q];
        float2 as2 = *(const float2*)(a_src + c0 + 2 * q);
        float2 ad2 = *(const float2*)(a_dst + c0 + 2 * q);
        ss = fmaf(hv.x, as2.x, fmaf(hv.y, as2.y, ss));
        sd = fmaf(hv.x, ad2.x, fmaf(hv.y, ad2.y, sd));
    }
    s_src[head * NCOL + n] = ss;
    s_dst[head * NCOL + n] = sd;
    __syncthreads();

    const float sdst = s_dst[head * NCOL + n];
    float e[NCOL];
    float m = -1e30f;
#pragma unroll
    for (int j = 0; j < NCOL; j++) {
        float v = lrelu(sdst + s_src[head * NCOL + j]);
        e[j] = v;
        m = fmaxf(m, v);
    }
    float sum = 0.f;
#pragma unroll
    for (int j = 0; j < NCOL; j++) {
        e[j] = __expf(e[j] - m);
        sum += e[j];
    }
    const float rinv = 1.f / sum;

    float a0 = 0.f, a1 = 0.f, a2 = 0.f, a3 = 0.f, a4 = 0.f, a5 = 0.f;
#pragma unroll
    for (int j = 0; j < NCOL; j++) {
        float2 h0 = *(const float2*)&h[j][c0 + 0];
        float2 h1 = *(const float2*)&h[j][c0 + 2];
        float2 h2 = *(const float2*)&h[j][c0 + 4];
        a0 = fmaf(e[j], h0.x, a0);
        a1 = fmaf(e[j], h0.y, a1);
        a2 = fmaf(e[j], h1.x, a2);
        a3 = fmaf(e[j], h1.y, a3);
        a4 = fmaf(e[j], h2.x, a4);
        a5 = fmaf(e[j], h2.y, a5);
    }
    hout[n][c0 + 0] = fmaf(a0, rinv, bias[c0 + 0]);
    hout[n][c0 + 1] = fmaf(a1, rinv, bias[c0 + 1]);
    hout[n][c0 + 2] = fmaf(a2, rinv, bias[c0 + 2]);
    hout[n][c0 + 3] = fmaf(a3, rinv, bias[c0 + 3]);
    hout[n][c0 + 4] = fmaf(a4, rinv, bias[c0 + 4]);
    hout[n][c0 + 5] = fmaf(a5, rinv, bias[c0 + 5]);
    __syncthreads();
}

__global__ void __launch_bounds__(THREADS, 6) gat_fused_kernel(
    const float* __restrict__ xs,       // [B, R, 32]
    const float* __restrict__ pe,       // [B, 32, 15]
    const float* __restrict__ W1,       // [16, 128]
    const float* __restrict__ as1, const float* __restrict__ ad1,
    const float* __restrict__ b1,
    const float* __restrict__ W2,       // [128, 128]
    const float* __restrict__ as2, const float* __restrict__ ad2,
    const float* __restrict__ b2,
    const float* __restrict__ W3,       // [128, 24]
    const float* __restrict__ as3, const float* __restrict__ ad3,
    const float* __restrict__ b3,
    const float* __restrict__ lw,       // [24, 64]
    const float* __restrict__ lb,       // [64]
    float* __restrict__ out,            // [B*R, 64]
    int R)
{
    __shared__ float hA[NCOL][FHP];
    __shared__ float hB[NCOL][FHP];
    __shared__ float s_src[HEADS * NCOL];
    __shared__ float s_dst[HEADS * NCOL];
    __shared__ float xin[NCOL][16];
    __shared__ float cs[F3];

    const int g = blockIdx.x;
    const int b = g / R;
    const int r = g - b * R;
    const int t = threadIdx.x;

    // ---- build input features ----
    for (int idx = t; idx < NCOL * 16; idx += THREADS) {
        int n = idx >> 4, f = idx & 15;
        float v;
        if (f == 0) v = xs[(size_t)(b * R + r) * NCOL + n];
        else        v = pe[(b * NCOL + n) * 15 + (f - 1)];
        xin[n][f] = v;
    }
    __syncthreads();

    // ---- layer 1 GEMM: hA[n][t] = sum_f xin[n][f] * W1[f][t] ----
    {
        float w[16];
#pragma unroll
        for (int f = 0; f < 16; f++) w[f] = W1[f * FH + t];
#pragma unroll 4
        for (int n = 0; n < NCOL; n++) {
            const float4* xr = (const float4*)&xin[n][0];
            float acc = 0.f;
#pragma unroll
            for (int q = 0; q < 4; q++) {
                float4 xv = xr[q];
                acc = fmaf(xv.x, w[4*q+0], acc);
                acc = fmaf(xv.y, w[4*q+1], acc);
                acc = fmaf(xv.z, w[4*q+2], acc);
                acc = fmaf(xv.w, w[4*q+3], acc);
            }
            hA[n][t] = acc;
        }
    }
    __syncthreads();
    gat_attention32(hA, hB, as1, ad1, b1, s_src, s_dst, t);

    // ---- layer 2 GEMM: 8-node x 4-channel register tile per thread ----
    // warp = node group (8 nodes), lane = channel group (4 channels).
    {
        const int cg = t & 31;          // lane -> channels 4cg..4cg+3
        const int ng = t >> 5;          // warp -> nodes 8ng..8ng+7
        const float* w2p = W2 + 4 * cg;
        float acc[8][4];
#pragma unroll
        for (int nn = 0; nn < 8; nn++)
#pragma unroll
            for (int cc = 0; cc < 4; cc++) acc[nn][cc] = 0.f;

        for (int f0 = 0; f0 < FH; f0 += 4) {
            float4 w0 = *(const float4*)(w2p + (f0 + 0) * FH);
            float4 w1 = *(const float4*)(w2p + (f0 + 1) * FH);
            float4 w2v = *(const float4*)(w2p + (f0 + 2) * FH);
            float4 w3v = *(const float4*)(w2p + (f0 + 3) * FH);
#pragma unroll
            for (int nn = 0; nn < 8; nn++) {
                float4 hv = *(const float4*)&hB[8 * ng + nn][f0];  // broadcast
                acc[nn][0] = fmaf(hv.x, w0.x, fmaf(hv.y, w1.x, fmaf(hv.z, w2v.x, fmaf(hv.w, w3v.x, acc[nn][0]))));
                acc[nn][1] = fmaf(hv.x, w0.y, fmaf(hv.y, w1.y, fmaf(hv.z, w2v.y, fmaf(hv.w, w3v.y, acc[nn][1]))));
                acc[nn][2] = fmaf(hv.x, w0.z, fmaf(hv.y, w1.z, fmaf(hv.z, w2v.z, fmaf(hv.w, w3v.z, acc[nn][2]))));
                acc[nn][3] = fmaf(hv.x, w0.w, fmaf(hv.y, w1.w, fmaf(hv.z, w2v.w, fmaf(hv.w, w3v.w, acc[nn][3]))));
            }
        }
#pragma unroll
        for (int nn = 0; nn < 8; nn++) {
            float4 o; o.x = acc[nn][0]; o.y = acc[nn][1]; o.z = acc[nn][2]; o.w = acc[nn][3];
            *(float4*)&hA[8 * ng + nn][4 * cg] = o;
        }
    }
    __syncthreads();
    gat_attention32(hA, hB, as2, ad2, b2, s_src, s_dst, t);

    // ---- layer 3 GEMM: 192 (node, 4-channel) units over 128 threads ----
#pragma unroll
    for (int pass = 0; pass < 2; pass++) {
        int u = t + pass * THREADS;
        if (u < 192) {
            int n = u / 6;
            int gq = u - n * 6;                 // channel quad 0..5
            const float* w3p = W3 + 4 * gq;
            float a0 = 0.f, a1 = 0.f, a2 = 0.f, a3 = 0.f;
#pragma unroll 4
            for (int f0 = 0; f0 < FH; f0 += 4) {
                float4 hv = *(const float4*)&hB[n][f0];
                float4 q0 = *(const float4*)(w3p + (f0 + 0) * F3);
                float4 q1 = *(const float4*)(w3p + (f0 + 1) * F3);
                float4 q2 = *(const float4*)(w3p + (f0 + 2) * F3);
                float4 q3 = *(const float4*)(w3p + (f0 + 3) * F3);
                a0 = fmaf(hv.x, q0.x, fmaf(hv.y, q1.x, fmaf(hv.z, q2.x, fmaf(hv.w, q3.x, a0))));
                a1 = fmaf(hv.x, q0.y, fmaf(hv.y, q1.y, fmaf(hv.z, q2.y, fmaf(hv.w, q3.y, a1))));
                a2 = fmaf(hv.x, q0.z, fmaf(hv.y, q1.z, fmaf(hv.z, q2.z, fmaf(hv.w, q3.z, a2))));
                a3 = fmaf(hv.x, q0.w, fmaf(hv.y, q1.w, fmaf(hv.z, q2.w, fmaf(hv.w, q3.w, a3))));
            }
            float4 o; o.x = a0; o.y = a1; o.z = a2; o.w = a3;
            *(float4*)&hA[n][4 * gq] = o;
        }
    }
    __syncthreads();
    gat_attention6(hA, hB, as3, ad3, b3, s_src, s_dst, t);

    // ---- final: mean over nodes commutes with linear ----
    if (t < F3) {
        float s = 0.f;
#pragma unroll
        for (int n = 0; n < NCOL; n++) s += hB[n][t];
        cs[t] = s * (1.f / 32.f);
    }
    __syncthreads();
    if (t < 64) {
        float acc = lb[t];
#pragma unroll
        for (int k = 0; k < F3; k++) acc = fmaf(cs[k], lw[k * 64 + t], acc);
        out[(size_t)g * 64 + t] = acc;
    }
}

extern "C" void kernel_launch(void* const* d_in, const int* in_sizes, int n_in,
                              void* d_out, int out_size)
{
    const float* xs  = (const float*)d_in[0];
    const float* pe  = (const float*)d_in[1];
    const float* W1  = (const float*)d_in[2];
    const float* as1 = (const float*)d_in[3];
    const float* ad1 = (const float*)d_in[4];
    const float* b1  = (const float*)d_in[5];
    const float* W2  = (const float*)d_in[6];
    const float* as2 = (const float*)d_in[7];
    const float* ad2 = (const float*)d_in[8];
    const float* b2  = (const float*)d_in[9];
    const float* W3  = (const float*)d_in[10];
    const float* as3 = (const float*)d_in[11];
    const float* ad3 = (const float*)d_in[12];
    const float* b3  = (const float*)d_in[13];
    const float* lw  = (const float*)d_in[14];
    const float* lb  = (const float*)d_in[15];
    float* out = (float*)d_out;

    int B = in_sizes[1] / (32 * 15);
    int R = in_sizes[0] / (B * 32);
    int G = B * R;

    gat_fused_kernel<<<G, THREADS>>>(xs, pe, W1, as1, ad1, b1,
                                     W2, as2, ad2, b2,
                                     W3, as3, ad3, b3,
                                     lw, lb, out, R);
}

// round 4
// speedup vs baseline: 2.4537x; 1.0347x over previous
#include <cuda_runtime.h>

// GAT over 16384 independent 32-node cliques, fully fused: one CTA per graph.
// Single in-place h buffer; attention aggregation runs as an alpha@h register-
// tiled GEMM with a bank-rotation swizzled alpha matrix in shared memory.

#define NCOL 32
#define HEADS 4
#define FH 128          // H * HID
#define FHP 132         // padded h row (floats)
#define F3 24           // H * OUT
#define THREADS 128
#define NEG_SLOPE 0.2f

__device__ __forceinline__ float lrelu(float x) { return x > 0.f ? x : NEG_SLOPE * x; }

// ---- attention for D=32 heads (layers 1 & 2), in-place on h ----
__device__ __forceinline__ void gat_attention32(
    float (*__restrict__ h)[FHP],
    const float* __restrict__ a_src, const float* __restrict__ a_dst,
    const float* __restrict__ bias,
    float* __restrict__ s_src, float* __restrict__ s_dst,
    float (*__restrict__ alpha)[NCOL],   // this head's 32x32, rotated cols
    int t)
{
    const int head = t >> 5;
    const int lane = t & 31;
    const int c0 = head * 32;

    // phase 1: scores for node n = lane
    {
        float ss = 0.f, sd = 0.f;
#pragma unroll
        for (int q = 0; q < 8; q++) {
            float4 hv  = *(const float4*)&h[lane][c0 + 4 * q];
            float4 as4 = ((const float4*)(a_src + c0))[q];
            float4 ad4 = ((const float4*)(a_dst + c0))[q];
            ss = fmaf(hv.x, as4.x, fmaf(hv.y, as4.y, fmaf(hv.z, as4.z, fmaf(hv.w, as4.w, ss))));
            sd = fmaf(hv.x, ad4.x, fmaf(hv.y, ad4.y, fmaf(hv.z, ad4.z, fmaf(hv.w, ad4.w, sd))));
        }
        s_src[head * NCOL + lane] = ss;
        s_dst[head * NCOL + lane] = sd;
    }
    __syncwarp();   // s_src/s_dst are warp-local (per head)

    // phase 2: softmax for target n = lane; store rotated, rinv-scaled alpha
    {
        const float sdst = s_dst[head * NCOL + lane];
        float e[NCOL];
        float m = -1e30f;
#pragma unroll
        for (int q = 0; q < 8; q++) {
            float4 sv = *(const float4*)&s_src[head * NCOL + 4 * q];
            e[4*q+0] = lrelu(sdst + sv.x);
            e[4*q+1] = lrelu(sdst + sv.y);
            e[4*q+2] = lrelu(sdst + sv.z);
            e[4*q+3] = lrelu(sdst + sv.w);
        }
#pragma unroll
        for (int j = 0; j < NCOL; j++) m = fmaxf(m, e[j]);
        float sum = 0.f;
#pragma unroll
        for (int j = 0; j < NCOL; j++) {
            e[j] = __expf(e[j] - m);
            sum += e[j];
        }
        const float rinv = 1.f / sum;
        const int rot = lane >> 2;                 // row-group id
#pragma unroll
        for (int q = 0; q < 8; q++) {
            int col = ((q + rot) & 7) * 4;
            float4 v;
            v.x = e[4*q+0] * rinv;
            v.y = e[4*q+1] * rinv;
            v.z = e[4*q+2] * rinv;
            v.w = e[4*q+3] * rinv;
            *(float4*)&alpha[lane][col] = v;
        }
    }
    __syncwarp();   // alpha is warp-local

    // phase 3: aggregation GEMM  out(32x32) = alpha(32x32) @ h(32x32 of this head)
    // lane tile: 4 targets (ng = lane>>2) x 8 channels (cg = lane&3)
    const int ng = lane >> 2;
    const int cg = lane & 3;
    const int cb = c0 + 8 * cg;
    float acc[4][8];
#pragma unroll
    for (int i = 0; i < 4; i++)
#pragma unroll
        for (int c = 0; c < 8; c++) acc[i][c] = 0.f;

#pragma unroll
    for (int j0 = 0; j0 < NCOL; j0 += 4) {
        float4 av[4];
        const int colb = (((j0 >> 2) + ng) & 7) * 4;
#pragma unroll
        for (int i = 0; i < 4; i++)
            av[i] = *(const float4*)&alpha[4 * ng + i][colb];
#pragma unroll
        for (int jj = 0; jj < 4; jj++) {
            float4 h0 = *(const float4*)&h[j0 + jj][cb];
            float4 h1 = *(const float4*)&h[j0 + jj][cb + 4];
            float aj[4];
#pragma unroll
            for (int i = 0; i < 4; i++) aj[i] = ((const float*)&av[i])[jj];
#pragma unroll
            for (int i = 0; i < 4; i++) {
                acc[i][0] = fmaf(aj[i], h0.x, acc[i][0]);
                acc[i][1] = fmaf(aj[i], h0.y, acc[i][1]);
                acc[i][2] = fmaf(aj[i], h0.z, acc[i][2]);
                acc[i][3] = fmaf(aj[i], h0.w, acc[i][3]);
                acc[i][4] = fmaf(aj[i], h1.x, acc[i][4]);
                acc[i][5] = fmaf(aj[i], h1.y, acc[i][5]);
                acc[i][6] = fmaf(aj[i], h1.z, acc[i][6]);
                acc[i][7] = fmaf(aj[i], h1.w, acc[i][7]);
            }
        }
    }
    __syncthreads();   // everyone done reading h

    const float4 b0 = *(const float4*)&bias[cb];
    const float4 b1 = *(const float4*)&bias[cb + 4];
#pragma unroll
    for (int i = 0; i < 4; i++) {
        int row = 4 * ng + i;
        float4 o0, o1;
        o0.x = acc[i][0] + b0.x; o0.y = acc[i][1] + b0.y;
        o0.z = acc[i][2] + b0.z; o0.w = acc[i][3] + b0.w;
        o1.x = acc[i][4] + b1.x; o1.y = acc[i][5] + b1.y;
        o1.z = acc[i][6] + b1.z; o1.w = acc[i][7] + b1.w;
        *(float4*)&h[row][cb]     = o0;
        *(float4*)&h[row][cb + 4] = o1;
    }
    __syncthreads();
}

// ---- attention for D=6 (layer 3), in-place ----
__device__ __forceinline__ void gat_attention6(
    float (*__restrict__ h)[FHP],
    const float* __restrict__ a_src, const float* __restrict__ a_dst,
    const float* __restrict__ bias,
    float* __restrict__ s_src, float* __restrict__ s_dst, int t)
{
    const int head = t >> 5;
    const int n = t & 31;
    const int c0 = head * 6;

    float ss = 0.f, sd = 0.f;
#pragma unroll
    for (int q = 0; q < 3; q++) {
        float2 hv  = *(const float2*)&h[n][c0 + 2 * q];
        float2 as2 = *(const float2*)(a_src + c0 + 2 * q);
        float2 ad2 = *(const float2*)(a_dst + c0 + 2 * q);
        ss = fmaf(hv.x, as2.x, fmaf(hv.y, as2.y, ss));
        sd = fmaf(hv.x, ad2.x, fmaf(hv.y, ad2.y, sd));
    }
    s_src[head * NCOL + n] = ss;
    s_dst[head * NCOL + n] = sd;
    __syncwarp();

    const float sdst = s_dst[head * NCOL + n];
    float e[NCOL];
    float m = -1e30f;
#pragma unroll
    for (int q = 0; q < 8; q++) {
        float4 sv = *(const float4*)&s_src[head * NCOL + 4 * q];
        e[4*q+0] = lrelu(sdst + sv.x);
        e[4*q+1] = lrelu(sdst + sv.y);
        e[4*q+2] = lrelu(sdst + sv.z);
        e[4*q+3] = lrelu(sdst + sv.w);
    }
#pragma unroll
    for (int j = 0; j < NCOL; j++) m = fmaxf(m, e[j]);
    float sum = 0.f;
#pragma unroll
    for (int j = 0; j < NCOL; j++) {
        e[j] = __expf(e[j] - m);
        sum += e[j];
    }
    const float rinv = 1.f / sum;

    float a0 = 0.f, a1 = 0.f, a2 = 0.f, a3 = 0.f, a4 = 0.f, a5 = 0.f;
#pragma unroll
    for (int j = 0; j < NCOL; j++) {
        float2 h0 = *(const float2*)&h[j][c0 + 0];
        float2 h1 = *(const float2*)&h[j][c0 + 2];
        float2 h2 = *(const float2*)&h[j][c0 + 4];
        a0 = fmaf(e[j], h0.x, a0);
        a1 = fmaf(e[j], h0.y, a1);
        a2 = fmaf(e[j], h1.x, a2);
        a3 = fmaf(e[j], h1.y, a3);
        a4 = fmaf(e[j], h2.x, a4);
        a5 = fmaf(e[j], h2.y, a5);
    }
    __syncthreads();   // everyone done reading h
    h[n][c0 + 0] = fmaf(a0, rinv, bias[c0 + 0]);
    h[n][c0 + 1] = fmaf(a1, rinv, bias[c0 + 1]);
    h[n][c0 + 2] = fmaf(a2, rinv, bias[c0 + 2]);
    h[n][c0 + 3] = fmaf(a3, rinv, bias[c0 + 3]);
    h[n][c0 + 4] = fmaf(a4, rinv, bias[c0 + 4]);
    h[n][c0 + 5] = fmaf(a5, rinv, bias[c0 + 5]);
    __syncthreads();
}

__global__ void __launch_bounds__(THREADS, 6) gat_fused_kernel(
    const float* __restrict__ xs,       // [B, R, 32]
    const float* __restrict__ pe,       // [B, 32, 15]
    const float* __restrict__ W1,       // [16, 128]
    const float* __restrict__ as1, const float* __restrict__ ad1,
    const float* __restrict__ b1,
    const float* __restrict__ W2,       // [128, 128]
    const float* __restrict__ as2, const float* __restrict__ ad2,
    const float* __restrict__ b2,
    const float* __restrict__ W3,       // [128, 24]
    const float* __restrict__ as3, const float* __restrict__ ad3,
    const float* __restrict__ b3,
    const float* __restrict__ lw,       // [24, 64]
    const float* __restrict__ lb,       // [64]
    float* __restrict__ out,            // [B*R, 64]
    int R)
{
    __shared__ float hs[NCOL][FHP];                 // 16.9 KB, single buffer
    __shared__ float alphas[HEADS][NCOL][NCOL];     // 16 KB
    __shared__ float s_src[HEADS * NCOL];
    __shared__ float s_dst[HEADS * NCOL];
    __shared__ float xin[NCOL][16];
    __shared__ float cs[F3];

    const int g = blockIdx.x;
    const int b = g / R;
    const int r = g - b * R;
    const int t = threadIdx.x;
    const int lane = t & 31;
    const int w = t >> 5;

    // ---- build input features ----
    for (int idx = t; idx < NCOL * 16; idx += THREADS) {
        int n = idx >> 4, f = idx & 15;
        float v;
        if (f == 0) v = xs[(size_t)(b * R + r) * NCOL + n];
        else        v = pe[(b * NCOL + n) * 15 + (f - 1)];
        xin[n][f] = v;
    }
    __syncthreads();

    // ---- layer 1 GEMM: 8-node x 4-channel tiles (warp=8 nodes, lane=4 ch) ----
    {
        const int cg = lane;            // channels 4cg..4cg+3
        const int ng = w;               // nodes 8ng..8ng+7
        const float* w1p = W1 + 4 * cg;
        float acc[8][4];
#pragma unroll
        for (int nn = 0; nn < 8; nn++)
#pragma unroll
            for (int c = 0; c < 4; c++) acc[nn][c] = 0.f;
#pragma unroll
        for (int f0 = 0; f0 < 16; f0 += 4) {
            float4 w0 = *(const float4*)(w1p + (f0 + 0) * FH);
            float4 w1v = *(const float4*)(w1p + (f0 + 1) * FH);
            float4 w2v = *(const float4*)(w1p + (f0 + 2) * FH);
            float4 w3v = *(const float4*)(w1p + (f0 + 3) * FH);
#pragma unroll
            for (int nn = 0; nn < 8; nn++) {
                float4 hv = *(const float4*)&xin[8 * ng + nn][f0];
                acc[nn][0] = fmaf(hv.x, w0.x, fmaf(hv.y, w1v.x, fmaf(hv.z, w2v.x, fmaf(hv.w, w3v.x, acc[nn][0]))));
                acc[nn][1] = fmaf(hv.x, w0.y, fmaf(hv.y, w1v.y, fmaf(hv.z, w2v.y, fmaf(hv.w, w3v.y, acc[nn][1]))));
                acc[nn][2] = fmaf(hv.x, w0.z, fmaf(hv.y, w1v.z, fmaf(hv.z, w2v.z, fmaf(hv.w, w3v.z, acc[nn][2]))));
                acc[nn][3] = fmaf(hv.x, w0.w, fmaf(hv.y, w1v.w, fmaf(hv.z, w2v.w, fmaf(hv.w, w3v.w, acc[nn][3]))));
            }
        }
#pragma unroll
        for (int nn = 0; nn < 8; nn++) {
            float4 o; o.x = acc[nn][0]; o.y = acc[nn][1]; o.z = acc[nn][2]; o.w = acc[nn][3];
            *(float4*)&hs[8 * ng + nn][4 * cg] = o;
        }
    }
    __syncthreads();
    gat_attention32(hs, as1, ad1, b1, s_src, s_dst, alphas[w], t);

    // ---- layer 2 GEMM: warp = 16 nodes x 64 channels; lane tile 8n x 4c ----
    {
        const int c_base = 64 * (w & 1);
        const int n_base = 16 * (w >> 1);
        const int cg = lane & 15;       // 16 channel groups of 4
        const int ng = lane >> 4;       // 2 node groups of 8
        const float* w2p = W2 + c_base + 4 * cg;
        float acc[8][4];
#pragma unroll
        for (int nn = 0; nn < 8; nn++)
#pragma unroll
            for (int c = 0; c < 4; c++) acc[nn][c] = 0.f;

#pragma unroll 2
        for (int f0 = 0; f0 < FH; f0 += 4) {
            float4 w0 = *(const float4*)(w2p + (f0 + 0) * FH);
            float4 w1v = *(const float4*)(w2p + (f0 + 1) * FH);
            float4 w2v = *(const float4*)(w2p + (f0 + 2) * FH);
            float4 w3v = *(const float4*)(w2p + (f0 + 3) * FH);
#pragma unroll
            for (int nn = 0; nn < 8; nn++) {
                float4 hv = *(const float4*)&hs[n_base + 8 * ng + nn][f0];
                acc[nn][0] = fmaf(hv.x, w0.x, fmaf(hv.y, w1v.x, fmaf(hv.z, w2v.x, fmaf(hv.w, w3v.x, acc[nn][0]))));
                acc[nn][1] = fmaf(hv.x, w0.y, fmaf(hv.y, w1v.y, fmaf(hv.z, w2v.y, fmaf(hv.w, w3v.y, acc[nn][1]))));
                acc[nn][2] = fmaf(hv.x, w0.z, fmaf(hv.y, w1v.z, fmaf(hv.z, w2v.z, fmaf(hv.w, w3v.z, acc[nn][2]))));
                acc[nn][3] = fmaf(hv.x, w0.w, fmaf(hv.y, w1v.w, fmaf(hv.z, w2v.w, fmaf(hv.w, w3v.w, acc[nn][3]))));
            }
        }
        __syncthreads();   // all reads of hs complete
#pragma unroll
        for (int nn = 0; nn < 8; nn++) {
            float4 o; o.x = acc[nn][0]; o.y = acc[nn][1]; o.z = acc[nn][2]; o.w = acc[nn][3];
            *(float4*)&hs[n_base + 8 * ng + nn][c_base + 4 * cg] = o;
        }
    }
    __syncthreads();
    gat_attention32(hs, as2, ad2, b2, s_src, s_dst, alphas[w], t);

    // ---- layer 3 GEMM: 192 (node, 4-channel) units, reg-staged in-place ----
    {
        float a[2][4];
        int n_[2], gq_[2];
#pragma unroll
        for (int pass = 0; pass < 2; pass++) {
            int u = t + pass * THREADS;
            n_[pass] = -1;
            if (u < 192) {
                int n = u / 6;
                int gq = u - n * 6;
                n_[pass] = n; gq_[pass] = gq;
                const float* w3p = W3 + 4 * gq;
                float a0 = 0.f, a1 = 0.f, a2 = 0.f, a3 = 0.f;
#pragma unroll 4
                for (int f0 = 0; f0 < FH; f0 += 4) {
                    float4 hv = *(const float4*)&hs[n][f0];
                    float4 q0 = *(const float4*)(w3p + (f0 + 0) * F3);
                    float4 q1 = *(const float4*)(w3p + (f0 + 1) * F3);
                    float4 q2 = *(const float4*)(w3p + (f0 + 2) * F3);
                    float4 q3 = *(const float4*)(w3p + (f0 + 3) * F3);
                    a0 = fmaf(hv.x, q0.x, fmaf(hv.y, q1.x, fmaf(hv.z, q2.x, fmaf(hv.w, q3.x, a0))));
                    a1 = fmaf(hv.x, q0.y, fmaf(hv.y, q1.y, fmaf(hv.z, q2.y, fmaf(hv.w, q3.y, a1))));
                    a2 = fmaf(hv.x, q0.z, fmaf(hv.y, q1.z, fmaf(hv.z, q2.z, fmaf(hv.w, q3.z, a2))));
                    a3 = fmaf(hv.x, q0.w, fmaf(hv.y, q1.w, fmaf(hv.z, q2.w, fmaf(hv.w, q3.w, a3))));
                }
                a[pass][0] = a0; a[pass][1] = a1; a[pass][2] = a2; a[pass][3] = a3;
            }
        }
        __syncthreads();   // all reads of hs complete
#pragma unroll
        for (int pass = 0; pass < 2; pass++) {
            if (n_[pass] >= 0) {
                float4 o; o.x = a[pass][0]; o.y = a[pass][1]; o.z = a[pass][2]; o.w = a[pass][3];
                *(float4*)&hs[n_[pass]][4 * gq_[pass]] = o;
            }
        }
    }
    __syncthreads();
    gat_attention6(hs, as3, ad3, b3, s_src, s_dst, t);

    // ---- final: mean over nodes commutes with linear ----
    if (t < F3) {
        float s = 0.f;
#pragma unroll
        for (int n = 0; n < NCOL; n++) s += hs[n][t];
        cs[t] = s * (1.f / 32.f);
    }
    __syncthreads();
    if (t < 64) {
        float acc = lb[t];
#pragma unroll
        for (int k = 0; k < F3; k++) acc = fmaf(cs[k], lw[k * 64 + t], acc);
        out[(size_t)g * 64 + t] = acc;
    }
}

extern "C" void kernel_launch(void* const* d_in, const int* in_sizes, int n_in,
                              void* d_out, int out_size)
{
    const float* xs  = (const float*)d_in[0];
    const float* pe  = (const float*)d_in[1];
    const float* W1  = (const float*)d_in[2];
    const float* as1 = (const float*)d_in[3];
    const float* ad1 = (const float*)d_in[4];
    const float* b1  = (const float*)d_in[5];
    const float* W2  = (const float*)d_in[6];
    const float* as2 = (const float*)d_in[7];
    const float* ad2 = (const float*)d_in[8];
    const float* b2  = (const float*)d_in[9];
    const float* W3  = (const float*)d_in[10];
    const float* as3 = (const float*)d_in[11];
    const float* ad3 = (const float*)d_in[12];
    const float* b3  = (const float*)d_in[13];
    const float* lw  = (const float*)d_in[14];
    const float* lb  = (const float*)d_in[15];
    float* out = (float*)d_out;

    int B = in_sizes[1] / (32 * 15);
    int R = in_sizes[0] / (B * 32);
    int G = B * R;

    gat_fused_kernel<<<G, THREADS>>>(xs, pe, W1, as1, ad1, b1,
                                     W2, as2, ad2, b2,
                                     W3, as3, ad3, b3,
                                     lw, lb, out, R);
}

// round 5
// speedup vs baseline: 2.6294x; 1.0716x over previous
#include <cuda_runtime.h>

// GAT over 16384 independent 32-node cliques, fully fused: one CTA per graph.
// All GEMMs use bank-exact tiles: consecutive-row LDS.128 (1 wavefront) and
// 128B-span LDG.128 for weights. W3 is pre-padded to [128][32] (head stride 8).

#define NCOL 32
#define HEADS 4
#define FH 128          // H * HID
#define FHP 132         // padded h row (floats); stride%32==4 -> consecutive rows conflict-free
#define F3 24           // H * OUT
#define XINP 20         // padded xin row; stride%32==20 -> consecutive rows conflict-free
#define THREADS 128
#define NEG_SLOPE 0.2f

__device__ float W3p_g[FH * 32];   // W3 padded: [f][head*8 + d], zeros at d=6,7

__device__ __forceinline__ float lrelu(float x) { return x > 0.f ? x : NEG_SLOPE * x; }

__global__ void pad_w3_kernel(const float* __restrict__ W3) {
    int idx = blockIdx.x * blockDim.x + threadIdx.x;   // 0..4095
    int f = idx >> 5, hp = idx & 31;
    int d = hp & 7, head = hp >> 3;
    W3p_g[idx] = (d < 6) ? W3[f * F3 + head * 6 + d] : 0.f;
}

// ---- attention for D=32 heads (layers 1 & 2), in-place on h ----
__device__ __forceinline__ void gat_attention32(
    float (*__restrict__ h)[FHP],
    const float* __restrict__ a_src, const float* __restrict__ a_dst,
    const float* __restrict__ bias,
    float* __restrict__ s_src, float* __restrict__ s_dst,
    float (*__restrict__ alpha)[NCOL], int t)
{
    const int head = t >> 5;
    const int lane = t & 31;
    const int c0 = head * 32;

    // phase 1: scores for node n = lane
    {
        float ss = 0.f, sd = 0.f;
#pragma unroll
        for (int q = 0; q < 8; q++) {
            float4 hv  = *(const float4*)&h[lane][c0 + 4 * q];
            float4 as4 = ((const float4*)(a_src + c0))[q];
            float4 ad4 = ((const float4*)(a_dst + c0))[q];
            ss = fmaf(hv.x, as4.x, fmaf(hv.y, as4.y, fmaf(hv.z, as4.z, fmaf(hv.w, as4.w, ss))));
            sd = fmaf(hv.x, ad4.x, fmaf(hv.y, ad4.y, fmaf(hv.z, ad4.z, fmaf(hv.w, ad4.w, sd))));
        }
        s_src[head * NCOL + lane] = ss;
        s_dst[head * NCOL + lane] = sd;
    }
    __syncwarp();

    // phase 2: softmax; store rotated, rinv-scaled alpha
    {
        const float sdst = s_dst[head * NCOL + lane];
        float e[NCOL];
        float m = -1e30f;
#pragma unroll
        for (int q = 0; q < 8; q++) {
            float4 sv = *(const float4*)&s_src[head * NCOL + 4 * q];
            e[4*q+0] = lrelu(sdst + sv.x);
            e[4*q+1] = lrelu(sdst + sv.y);
            e[4*q+2] = lrelu(sdst + sv.z);
            e[4*q+3] = lrelu(sdst + sv.w);
        }
#pragma unroll
        for (int j = 0; j < NCOL; j++) m = fmaxf(m, e[j]);
        float sum = 0.f;
#pragma unroll
        for (int j = 0; j < NCOL; j++) {
            e[j] = __expf(e[j] - m);
            sum += e[j];
        }
        const float rinv = 1.f / sum;
        const int rot = lane >> 2;
#pragma unroll
        for (int q = 0; q < 8; q++) {
            int col = ((q + rot) & 7) * 4;
            float4 v;
            v.x = e[4*q+0] * rinv;
            v.y = e[4*q+1] * rinv;
            v.z = e[4*q+2] * rinv;
            v.w = e[4*q+3] * rinv;
            *(float4*)&alpha[lane][col] = v;
        }
    }
    __syncwarp();

    // phase 3: aggregation GEMM out(32x32) = alpha @ h_head
    const int ng = lane >> 2;
    const int cg = lane & 3;
    const int cb = c0 + 8 * cg;
    float acc[4][8];
#pragma unroll
    for (int i = 0; i < 4; i++)
#pragma unroll
        for (int c = 0; c < 8; c++) acc[i][c] = 0.f;

#pragma unroll
    for (int j0 = 0; j0 < NCOL; j0 += 4) {
        float4 av[4];
        const int colb = (((j0 >> 2) + ng) & 7) * 4;
#pragma unroll
        for (int i = 0; i < 4; i++)
            av[i] = *(const float4*)&alpha[4 * ng + i][colb];
#pragma unroll
        for (int jj = 0; jj < 4; jj++) {
            float4 h0 = *(const float4*)&h[j0 + jj][cb];
            float4 h1 = *(const float4*)&h[j0 + jj][cb + 4];
            float aj[4];
#pragma unroll
            for (int i = 0; i < 4; i++) aj[i] = ((const float*)&av[i])[jj];
#pragma unroll
            for (int i = 0; i < 4; i++) {
                acc[i][0] = fmaf(aj[i], h0.x, acc[i][0]);
                acc[i][1] = fmaf(aj[i], h0.y, acc[i][1]);
                acc[i][2] = fmaf(aj[i], h0.z, acc[i][2]);
                acc[i][3] = fmaf(aj[i], h0.w, acc[i][3]);
                acc[i][4] = fmaf(aj[i], h1.x, acc[i][4]);
                acc[i][5] = fmaf(aj[i], h1.y, acc[i][5]);
                acc[i][6] = fmaf(aj[i], h1.z, acc[i][6]);
                acc[i][7] = fmaf(aj[i], h1.w, acc[i][7]);
            }
        }
    }
    __syncthreads();

    const float4 b0 = *(const float4*)&bias[cb];
    const float4 b1 = *(const float4*)&bias[cb + 4];
#pragma unroll
    for (int i = 0; i < 4; i++) {
        int row = 4 * ng + i;
        float4 o0, o1;
        o0.x = acc[i][0] + b0.x; o0.y = acc[i][1] + b0.y;
        o0.z = acc[i][2] + b0.z; o0.w = acc[i][3] + b0.w;
        o1.x = acc[i][4] + b1.x; o1.y = acc[i][5] + b1.y;
        o1.z = acc[i][6] + b1.z; o1.w = acc[i][7] + b1.w;
        *(float4*)&h[row][cb]     = o0;
        *(float4*)&h[row][cb + 4] = o1;
    }
    __syncthreads();
}

// ---- attention for D=6 (layer 3), padded layout: head d at col head*8+d ----
__device__ __forceinline__ void gat_attention6(
    float (*__restrict__ h)[FHP],
    const float* __restrict__ a_src, const float* __restrict__ a_dst,
    const float* __restrict__ bias,
    float* __restrict__ s_src, float* __restrict__ s_dst, int t)
{
    const int head = t >> 5;
    const int n = t & 31;
    const int cp = head * 8;        // padded col base
    const int c0 = head * 6;        // original index base (for a_src/bias)

    float ss = 0.f, sd = 0.f;
    {
        float4 hv0 = *(const float4*)&h[n][cp];
        float2 hv1 = *(const float2*)&h[n][cp + 4];
        ss = fmaf(hv0.x, a_src[c0+0], fmaf(hv0.y, a_src[c0+1], fmaf(hv0.z, a_src[c0+2],
             fmaf(hv0.w, a_src[c0+3], fmaf(hv1.x, a_src[c0+4], hv1.y * a_src[c0+5])))));
        sd = fmaf(hv0.x, a_dst[c0+0], fmaf(hv0.y, a_dst[c0+1], fmaf(hv0.z, a_dst[c0+2],
             fmaf(hv0.w, a_dst[c0+3], fmaf(hv1.x, a_dst[c0+4], hv1.y * a_dst[c0+5])))));
    }
    s_src[head * NCOL + n] = ss;
    s_dst[head * NCOL + n] = sd;
    __syncwarp();

    const float sdst = s_dst[head * NCOL + n];
    float e[NCOL];
    float m = -1e30f;
#pragma unroll
    for (int q = 0; q < 8; q++) {
        float4 sv = *(const float4*)&s_src[head * NCOL + 4 * q];
        e[4*q+0] = lrelu(sdst + sv.x);
        e[4*q+1] = lrelu(sdst + sv.y);
        e[4*q+2] = lrelu(sdst + sv.z);
        e[4*q+3] = lrelu(sdst + sv.w);
    }
#pragma unroll
    for (int j = 0; j < NCOL; j++) m = fmaxf(m, e[j]);
    float sum = 0.f;
#pragma unroll
    for (int j = 0; j < NCOL; j++) {
        e[j] = __expf(e[j] - m);
        sum += e[j];
    }
    const float rinv = 1.f / sum;

    float a0 = 0.f, a1 = 0.f, a2 = 0.f, a3 = 0.f, a4 = 0.f, a5 = 0.f;
#pragma unroll
    for (int j = 0; j < NCOL; j++) {
        float4 h0 = *(const float4*)&h[j][cp];
        float2 h1 = *(const float2*)&h[j][cp + 4];
        a0 = fmaf(e[j], h0.x, a0);
        a1 = fmaf(e[j], h0.y, a1);
        a2 = fmaf(e[j], h0.z, a2);
        a3 = fmaf(e[j], h0.w, a3);
        a4 = fmaf(e[j], h1.x, a4);
        a5 = fmaf(e[j], h1.y, a5);
    }
    __syncthreads();
    h[n][cp + 0] = fmaf(a0, rinv, bias[c0 + 0]);
    h[n][cp + 1] = fmaf(a1, rinv, bias[c0 + 1]);
    h[n][cp + 2] = fmaf(a2, rinv, bias[c0 + 2]);
    h[n][cp + 3] = fmaf(a3, rinv, bias[c0 + 3]);
    h[n][cp + 4] = fmaf(a4, rinv, bias[c0 + 4]);
    h[n][cp + 5] = fmaf(a5, rinv, bias[c0 + 5]);
    __syncthreads();
}

__global__ void __launch_bounds__(THREADS, 6) gat_fused_kernel(
    const float* __restrict__ xs,
    const float* __restrict__ pe,
    const float* __restrict__ W1,
    const float* __restrict__ as1, const float* __restrict__ ad1,
    const float* __restrict__ b1,
    const float* __restrict__ W2,
    const float* __restrict__ as2, const float* __restrict__ ad2,
    const float* __restrict__ b2,
    const float* __restrict__ as3, const float* __restrict__ ad3,
    const float* __restrict__ b3,
    const float* __restrict__ lw,
    const float* __restrict__ lb,
    float* __restrict__ out,
    int R)
{
    __shared__ float hs[NCOL][FHP];                 // 16.9 KB
    __shared__ float alphas[HEADS][NCOL][NCOL];     // 16 KB
    __shared__ float s_src[HEADS * NCOL];
    __shared__ float s_dst[HEADS * NCOL];
    __shared__ float xin[NCOL][XINP];
    __shared__ float cs[F3];

    const int g = blockIdx.x;
    const int b = g / R;
    const int r = g - b * R;
    const int t = threadIdx.x;
    const int lane = t & 31;
    const int w = t >> 5;
    const int cq = lane & 7;        // channel quad within warp tile
    const int ngrp = lane >> 3;     // node sub-index within consecutive quad

    // ---- build input features ----
    for (int idx = t; idx < NCOL * 16; idx += THREADS) {
        int n = idx >> 4, f = idx & 15;
        float v;
        if (f == 0) v = xs[(size_t)(b * R + r) * NCOL + n];
        else        v = pe[(b * NCOL + n) * 15 + (f - 1)];
        xin[n][f] = v;
    }
    __syncthreads();

    // ---- layer 1 GEMM: warp w -> channels 32w..32w+31, all 32 nodes ----
    {
        const int cwb = 32 * w;
        const float* w1p = W1 + cwb + 4 * cq;
        float acc[8][4];
#pragma unroll
        for (int nn = 0; nn < 8; nn++)
#pragma unroll
            for (int c = 0; c < 4; c++) acc[nn][c] = 0.f;
#pragma unroll
        for (int f0 = 0; f0 < 16; f0 += 4) {
            float4 w0 = *(const float4*)(w1p + (f0 + 0) * FH);
            float4 w1v = *(const float4*)(w1p + (f0 + 1) * FH);
            float4 w2v = *(const float4*)(w1p + (f0 + 2) * FH);
            float4 w3v = *(const float4*)(w1p + (f0 + 3) * FH);
#pragma unroll
            for (int nn = 0; nn < 8; nn++) {
                float4 hv = *(const float4*)&xin[4 * nn + ngrp][f0];  // 4 consec rows: 1 wf
                acc[nn][0] = fmaf(hv.x, w0.x, fmaf(hv.y, w1v.x, fmaf(hv.z, w2v.x, fmaf(hv.w, w3v.x, acc[nn][0]))));
                acc[nn][1] = fmaf(hv.x, w0.y, fmaf(hv.y, w1v.y, fmaf(hv.z, w2v.y, fmaf(hv.w, w3v.y, acc[nn][1]))));
                acc[nn][2] = fmaf(hv.x, w0.z, fmaf(hv.y, w1v.z, fmaf(hv.z, w2v.z, fmaf(hv.w, w3v.z, acc[nn][2]))));
                acc[nn][3] = fmaf(hv.x, w0.w, fmaf(hv.y, w1v.w, fmaf(hv.z, w2v.w, fmaf(hv.w, w3v.w, acc[nn][3]))));
            }
        }
#pragma unroll
        for (int nn = 0; nn < 8; nn++) {
            float4 o; o.x = acc[nn][0]; o.y = acc[nn][1]; o.z = acc[nn][2]; o.w = acc[nn][3];
            *(float4*)&hs[4 * nn + ngrp][cwb + 4 * cq] = o;
        }
    }
    __syncthreads();
    gat_attention32(hs, as1, ad1, b1, s_src, s_dst, alphas[w], t);

    // ---- layer 2 GEMM: warp w -> channels 32w..32w+31, all 32 nodes ----
    {
        const int cwb = 32 * w;
        const float* w2p = W2 + cwb + 4 * cq;
        float acc[8][4];
#pragma unroll
        for (int nn = 0; nn < 8; nn++)
#pragma unroll
            for (int c = 0; c < 4; c++) acc[nn][c] = 0.f;

#pragma unroll 2
        for (int f0 = 0; f0 < FH; f0 += 4) {
            float4 w0 = *(const float4*)(w2p + (f0 + 0) * FH);
            float4 w1v = *(const float4*)(w2p + (f0 + 1) * FH);
            float4 w2v = *(const float4*)(w2p + (f0 + 2) * FH);
            float4 w3v = *(const float4*)(w2p + (f0 + 3) * FH);
#pragma unroll
            for (int nn = 0; nn < 8; nn++) {
                float4 hv = *(const float4*)&hs[4 * nn + ngrp][f0];   // 4 consec rows: 1 wf
                acc[nn][0] = fmaf(hv.x, w0.x, fmaf(hv.y, w1v.x, fmaf(hv.z, w2v.x, fmaf(hv.w, w3v.x, acc[nn][0]))));
                acc[nn][1] = fmaf(hv.x, w0.y, fmaf(hv.y, w1v.y, fmaf(hv.z, w2v.y, fmaf(hv.w, w3v.y, acc[nn][1]))));
                acc[nn][2] = fmaf(hv.x, w0.z, fmaf(hv.y, w1v.z, fmaf(hv.z, w2v.z, fmaf(hv.w, w3v.z, acc[nn][2]))));
                acc[nn][3] = fmaf(hv.x, w0.w, fmaf(hv.y, w1v.w, fmaf(hv.z, w2v.w, fmaf(hv.w, w3v.w, acc[nn][3]))));
            }
        }
        __syncthreads();   // all reads of hs complete before overwrite
#pragma unroll
        for (int nn = 0; nn < 8; nn++) {
            float4 o; o.x = acc[nn][0]; o.y = acc[nn][1]; o.z = acc[nn][2]; o.w = acc[nn][3];
            *(float4*)&hs[4 * nn + ngrp][cwb + 4 * cq] = o;
        }
    }
    __syncthreads();
    gat_attention32(hs, as2, ad2, b2, s_src, s_dst, alphas[w], t);

    // ---- layer 3 GEMM: warp w -> nodes 8w..8w+7, all 32 padded channels ----
    // Each warp reads/writes only its own 8 rows -> no internal sync needed.
    {
        const float* w3p = W3p_g + 4 * cq;
        float acc[2][4];
#pragma unroll
        for (int s = 0; s < 2; s++)
#pragma unroll
            for (int c = 0; c < 4; c++) acc[s][c] = 0.f;

#pragma unroll 4
        for (int f0 = 0; f0 < FH; f0 += 4) {
            float4 q0 = *(const float4*)(w3p + (f0 + 0) * 32);
            float4 q1 = *(const float4*)(w3p + (f0 + 1) * 32);
            float4 q2 = *(const float4*)(w3p + (f0 + 2) * 32);
            float4 q3 = *(const float4*)(w3p + (f0 + 3) * 32);
#pragma unroll
            for (int s = 0; s < 2; s++) {
                float4 hv = *(const float4*)&hs[8 * w + 4 * s + ngrp][f0];  // 4 consec rows
                acc[s][0] = fmaf(hv.x, q0.x, fmaf(hv.y, q1.x, fmaf(hv.z, q2.x, fmaf(hv.w, q3.x, acc[s][0]))));
                acc[s][1] = fmaf(hv.x, q0.y, fmaf(hv.y, q1.y, fmaf(hv.z, q2.y, fmaf(hv.w, q3.y, acc[s][1]))));
                acc[s][2] = fmaf(hv.x, q0.z, fmaf(hv.y, q1.z, fmaf(hv.z, q2.z, fmaf(hv.w, q3.z, acc[s][2]))));
                acc[s][3] = fmaf(hv.x, q0.w, fmaf(hv.y, q1.w, fmaf(hv.z, q2.w, fmaf(hv.w, q3.w, acc[s][3]))));
            }
        }
#pragma unroll
        for (int s = 0; s < 2; s++) {
            float4 o; o.x = acc[s][0]; o.y = acc[s][1]; o.z = acc[s][2]; o.w = acc[s][3];
            *(float4*)&hs[8 * w + 4 * s + ngrp][4 * cq] = o;
        }
    }
    __syncthreads();
    gat_attention6(hs, as3, ad3, b3, s_src, s_dst, t);

    // ---- final: mean over nodes commutes with linear (padded layout) ----
    if (t < F3) {
        int head = t / 6, d = t - head * 6;
        float s = 0.f;
#pragma unroll
        for (int n = 0; n < NCOL; n++) s += hs[n][head * 8 + d];
        cs[t] = s * (1.f / 32.f);
    }
    __syncthreads();
    if (t < 64) {
        float acc = lb[t];
#pragma unroll
        for (int k = 0; k < F3; k++) acc = fmaf(cs[k], lw[k * 64 + t], acc);
        out[(size_t)g * 64 + t] = acc;
    }
}

extern "C" void kernel_launch(void* const* d_in, const int* in_sizes, int n_in,
                              void* d_out, int out_size)
{
    const float* xs  = (const float*)d_in[0];
    const float* pe  = (const float*)d_in[1];
    const float* W1  = (const float*)d_in[2];
    const float* as1 = (const float*)d_in[3];
    const float* ad1 = (const float*)d_in[4];
    const float* b1  = (const float*)d_in[5];
    const float* W2  = (const float*)d_in[6];
    const float* as2 = (const float*)d_in[7];
    const float* ad2 = (const float*)d_in[8];
    const float* b2  = (const float*)d_in[9];
    const float* W3  = (const float*)d_in[10];
    const float* as3 = (const float*)d_in[11];
    const float* ad3 = (const float*)d_in[12];
    const float* b3  = (const float*)d_in[13];
    const float* lw  = (const float*)d_in[14];
    const float* lb  = (const float*)d_in[15];
    float* out = (float*)d_out;

    int B = in_sizes[1] / (32 * 15);
    int R = in_sizes[0] / (B * 32);
    int G = B * R;

    pad_w3_kernel<<<32, 128>>>(W3);
    gat_fused_kernel<<<G, THREADS>>>(xs, pe, W1, as1, ad1, b1,
                                     W2, as2, ad2, b2,
                                     as3, ad3, b3,
                                     lw, lb, out, R);
}

// round 6
// speedup vs baseline: 2.8005x; 1.0651x over previous
#include <cuda_runtime.h>

// GAT over 16384 independent 32-node cliques, fully fused: one CTA per graph.
// Bank-exact tiles + packed fp32x2 FFMA (fma.rn.f32x2): channel-paired
// accumulators with weight pairs loaded pre-packed from memory; broadcast
// scalars duplicated via 1 ALU mov (ALU pipe is idle).

#define NCOL 32
#define HEADS 4
#define FH 128          // H * HID
#define FHP 132         // padded h row; stride%32==4 -> consecutive rows conflict-free
#define F3 24           // H * OUT
#define XINP 20         // padded xin row
#define THREADS 128
#define NEG_SLOPE 0.2f

typedef unsigned long long u64;

__device__ float W3p_g[FH * 32];   // W3 padded: [f][head*8 + d], zeros at d=6,7

__device__ __forceinline__ float lrelu(float x) { return x > 0.f ? x : NEG_SLOPE * x; }

__device__ __forceinline__ u64 dup2(float x) {
    u64 r; asm("mov.b64 %0,{%1,%1};" : "=l"(r) : "f"(x)); return r;
}
__device__ __forceinline__ float2 unpack2(u64 v) {
    float2 r; asm("mov.b64 {%0,%1},%2;" : "=f"(r.x), "=f"(r.y) : "l"(v)); return r;
}
__device__ __forceinline__ void fma2(u64 &d, u64 a, u64 b) {
    asm("fma.rn.f32x2 %0,%1,%2,%0;" : "+l"(d) : "l"(a), "l"(b));
}
__device__ __forceinline__ void add2(u64 &d, u64 a) {
    asm("add.rn.f32x2 %0,%0,%1;" : "+l"(d) : "l"(a));
}

__global__ void pad_w3_kernel(const float* __restrict__ W3) {
    int idx = blockIdx.x * blockDim.x + threadIdx.x;   // 0..4095
    int f = idx >> 5, hp = idx & 31;
    int d = hp & 7, head = hp >> 3;
    W3p_g[idx] = (d < 6) ? W3[f * F3 + head * 6 + d] : 0.f;
}

// ---- attention for D=32 heads (layers 1 & 2), in-place on h ----
__device__ __forceinline__ void gat_attention32(
    float (*__restrict__ h)[FHP],
    const float* __restrict__ a_src, const float* __restrict__ a_dst,
    const float* __restrict__ bias,
    float* __restrict__ s_src, float* __restrict__ s_dst,
    float (*__restrict__ alpha)[NCOL], int t)
{
    const int head = t >> 5;
    const int lane = t & 31;
    const int c0 = head * 32;

    // phase 1: scores for node n = lane (k-packed: both operands contiguous)
    {
        const ulonglong2* hp = (const ulonglong2*)&h[lane][c0];
        const ulonglong2* ap = (const ulonglong2*)(a_src + c0);
        const ulonglong2* dp = (const ulonglong2*)(a_dst + c0);
        u64 ss2 = 0, sd2 = 0;
#pragma unroll
        for (int q = 0; q < 8; q++) {
            ulonglong2 hq = hp[q];
            ulonglong2 aq = ap[q];
            ulonglong2 dq = dp[q];
            fma2(ss2, hq.x, aq.x); fma2(ss2, hq.y, aq.y);
            fma2(sd2, hq.x, dq.x); fma2(sd2, hq.y, dq.y);
        }
        float2 s2 = unpack2(ss2);
        float2 d2 = unpack2(sd2);
        s_src[head * NCOL + lane] = s2.x + s2.y;
        s_dst[head * NCOL + lane] = d2.x + d2.y;
    }
    __syncwarp();

    // phase 2: softmax; store rotated, rinv-scaled alpha
    {
        const float sdst = s_dst[head * NCOL + lane];
        float e[NCOL];
        float m = -1e30f;
#pragma unroll
        for (int q = 0; q < 8; q++) {
            float4 sv = *(const float4*)&s_src[head * NCOL + 4 * q];
            e[4*q+0] = lrelu(sdst + sv.x);
            e[4*q+1] = lrelu(sdst + sv.y);
            e[4*q+2] = lrelu(sdst + sv.z);
            e[4*q+3] = lrelu(sdst + sv.w);
        }
#pragma unroll
        for (int j = 0; j < NCOL; j++) m = fmaxf(m, e[j]);
        float sum = 0.f;
#pragma unroll
        for (int j = 0; j < NCOL; j++) {
            e[j] = __expf(e[j] - m);
            sum += e[j];
        }
        const float rinv = 1.f / sum;
        const int rot = lane >> 2;
#pragma unroll
        for (int q = 0; q < 8; q++) {
            int col = ((q + rot) & 7) * 4;
            float4 v;
            v.x = e[4*q+0] * rinv;
            v.y = e[4*q+1] * rinv;
            v.z = e[4*q+2] * rinv;
            v.w = e[4*q+3] * rinv;
            *(float4*)&alpha[lane][col] = v;
        }
    }
    __syncwarp();

    // phase 3: aggregation GEMM out(32x32) = alpha @ h_head (channel-packed)
    const int ng = lane >> 2;
    const int cg = lane & 3;
    const int cb = c0 + 8 * cg;
    u64 acc2[4][4];
#pragma unroll
    for (int i = 0; i < 4; i++)
#pragma unroll
        for (int p = 0; p < 4; p++) acc2[i][p] = 0;

#pragma unroll
    for (int j0 = 0; j0 < NCOL; j0 += 4) {
        float4 av[4];
        const int colb = (((j0 >> 2) + ng) & 7) * 4;
#pragma unroll
        for (int i = 0; i < 4; i++)
            av[i] = *(const float4*)&alpha[4 * ng + i][colb];
#pragma unroll
        for (int jj = 0; jj < 4; jj++) {
            ulonglong2 h0 = *(const ulonglong2*)&h[j0 + jj][cb];      // ch pairs 0,1
            ulonglong2 h1 = *(const ulonglong2*)&h[j0 + jj][cb + 4];  // ch pairs 2,3
#pragma unroll
            for (int i = 0; i < 4; i++) {
                u64 a = dup2(((const float*)&av[i])[jj]);
                fma2(acc2[i][0], a, h0.x);
                fma2(acc2[i][1], a, h0.y);
                fma2(acc2[i][2], a, h1.x);
                fma2(acc2[i][3], a, h1.y);
            }
        }
    }
    __syncthreads();   // everyone done reading h

    ulonglong2 b01 = *(const ulonglong2*)&bias[cb];
    ulonglong2 b23 = *(const ulonglong2*)&bias[cb + 4];
#pragma unroll
    for (int i = 0; i < 4; i++) {
        int row = 4 * ng + i;
        u64 o0 = acc2[i][0], o1 = acc2[i][1], o2 = acc2[i][2], o3 = acc2[i][3];
        add2(o0, b01.x); add2(o1, b01.y); add2(o2, b23.x); add2(o3, b23.y);
        ulonglong2 s0; s0.x = o0; s0.y = o1;
        ulonglong2 s1; s1.x = o2; s1.y = o3;
        *(ulonglong2*)&h[row][cb]     = s0;
        *(ulonglong2*)&h[row][cb + 4] = s1;
    }
    __syncthreads();
}

// ---- attention for D=6 (layer 3), padded layout: head d at col head*8+d ----
__device__ __forceinline__ void gat_attention6(
    float (*__restrict__ h)[FHP],
    const float* __restrict__ a_src, const float* __restrict__ a_dst,
    const float* __restrict__ bias,
    float* __restrict__ s_src, float* __restrict__ s_dst, int t)
{
    const int head = t >> 5;
    const int n = t & 31;
    const int cp = head * 8;
    const int c0 = head * 6;

    float ss, sd;
    {
        float4 hv0 = *(const float4*)&h[n][cp];
        float2 hv1 = *(const float2*)&h[n][cp + 4];
        ss = fmaf(hv0.x, a_src[c0+0], fmaf(hv0.y, a_src[c0+1], fmaf(hv0.z, a_src[c0+2],
             fmaf(hv0.w, a_src[c0+3], fmaf(hv1.x, a_src[c0+4], hv1.y * a_src[c0+5])))));
        sd = fmaf(hv0.x, a_dst[c0+0], fmaf(hv0.y, a_dst[c0+1], fmaf(hv0.z, a_dst[c0+2],
             fmaf(hv0.w, a_dst[c0+3], fmaf(hv1.x, a_dst[c0+4], hv1.y * a_dst[c0+5])))));
    }
    s_src[head * NCOL + n] = ss;
    s_dst[head * NCOL + n] = sd;
    __syncwarp();

    const float sdst = s_dst[head * NCOL + n];
    float e[NCOL];
    float m = -1e30f;
#pragma unroll
    for (int q = 0; q < 8; q++) {
        float4 sv = *(const float4*)&s_src[head * NCOL + 4 * q];
        e[4*q+0] = lrelu(sdst + sv.x);
        e[4*q+1] = lrelu(sdst + sv.y);
        e[4*q+2] = lrelu(sdst + sv.z);
        e[4*q+3] = lrelu(sdst + sv.w);
    }
#pragma unroll
    for (int j = 0; j < NCOL; j++) m = fmaxf(m, e[j]);
    float sum = 0.f;
#pragma unroll
    for (int j = 0; j < NCOL; j++) {
        e[j] = __expf(e[j] - m);
        sum += e[j];
    }
    const float rinv = 1.f / sum;

    // channel-packed aggregation: 3 pairs
    u64 acc2[3] = {0, 0, 0};
#pragma unroll
    for (int j = 0; j < NCOL; j++) {
        u64 a = dup2(e[j]);
        ulonglong2 hh = *(const ulonglong2*)&h[j][cp];  // pairs (0,1),(2,3)
        u64 h2 = *(const u64*)&h[j][cp + 4];            // pair (4,5)
        fma2(acc2[0], a, hh.x);
        fma2(acc2[1], a, hh.y);
        fma2(acc2[2], a, h2);
    }
    float2 p0 = unpack2(acc2[0]);
    float2 p1 = unpack2(acc2[1]);
    float2 p2 = unpack2(acc2[2]);
    __syncthreads();   // everyone done reading h
    h[n][cp + 0] = fmaf(p0.x, rinv, bias[c0 + 0]);
    h[n][cp + 1] = fmaf(p0.y, rinv, bias[c0 + 1]);
    h[n][cp + 2] = fmaf(p1.x, rinv, bias[c0 + 2]);
    h[n][cp + 3] = fmaf(p1.y, rinv, bias[c0 + 3]);
    h[n][cp + 4] = fmaf(p2.x, rinv, bias[c0 + 4]);
    h[n][cp + 5] = fmaf(p2.y, rinv, bias[c0 + 5]);
    __syncthreads();
}

__global__ void __launch_bounds__(THREADS, 6) gat_fused_kernel(
    const float* __restrict__ xs,
    const float* __restrict__ pe,
    const float* __restrict__ W1,
    const float* __restrict__ as1, const float* __restrict__ ad1,
    const float* __restrict__ b1,
    const float* __restrict__ W2,
    const float* __restrict__ as2, const float* __restrict__ ad2,
    const float* __restrict__ b2,
    const float* __restrict__ as3, const float* __restrict__ ad3,
    const float* __restrict__ b3,
    const float* __restrict__ lw,
    const float* __restrict__ lb,
    float* __restrict__ out,
    int R)
{
    __shared__ float hs[NCOL][FHP];
    __shared__ float alphas[HEADS][NCOL][NCOL];
    __shared__ float s_src[HEADS * NCOL];
    __shared__ float s_dst[HEADS * NCOL];
    __shared__ float xin[NCOL][XINP];
    __shared__ float cs[F3];

    const int g = blockIdx.x;
    const int b = g / R;
    const int r = g - b * R;
    const int t = threadIdx.x;
    const int lane = t & 31;
    const int w = t >> 5;
    const int cq = lane & 7;
    const int ngrp = lane >> 3;

    // ---- build input features ----
    for (int idx = t; idx < NCOL * 16; idx += THREADS) {
        int n = idx >> 4, f = idx & 15;
        float v;
        if (f == 0) v = xs[(size_t)(b * R + r) * NCOL + n];
        else        v = pe[(b * NCOL + n) * 15 + (f - 1)];
        xin[n][f] = v;
    }
    __syncthreads();

    // ---- layer 1 GEMM: warp w -> channels 32w..32w+31 (channel-packed) ----
    {
        const int cwb = 32 * w;
        u64 acc2[8][2];
#pragma unroll
        for (int nn = 0; nn < 8; nn++) { acc2[nn][0] = 0; acc2[nn][1] = 0; }
#pragma unroll
        for (int f0 = 0; f0 < 16; f0 += 4) {
            ulonglong2 wv[4];
#pragma unroll
            for (int k = 0; k < 4; k++)
                wv[k] = *(const ulonglong2*)(W1 + (f0 + k) * FH + cwb + 4 * cq);
#pragma unroll
            for (int nn = 0; nn < 8; nn++) {
                float4 hv = *(const float4*)&xin[4 * nn + ngrp][f0];
                u64 d0 = dup2(hv.x), d1 = dup2(hv.y), d2 = dup2(hv.z), d3 = dup2(hv.w);
                fma2(acc2[nn][0], d0, wv[0].x); fma2(acc2[nn][1], d0, wv[0].y);
                fma2(acc2[nn][0], d1, wv[1].x); fma2(acc2[nn][1], d1, wv[1].y);
                fma2(acc2[nn][0], d2, wv[2].x); fma2(acc2[nn][1], d2, wv[2].y);
                fma2(acc2[nn][0], d3, wv[3].x); fma2(acc2[nn][1], d3, wv[3].y);
            }
        }
#pragma unroll
        for (int nn = 0; nn < 8; nn++) {
            ulonglong2 o; o.x = acc2[nn][0]; o.y = acc2[nn][1];
            *(ulonglong2*)&hs[4 * nn + ngrp][cwb + 4 * cq] = o;
        }
    }
    __syncthreads();
    gat_attention32(hs, as1, ad1, b1, s_src, s_dst, alphas[w], t);

    // ---- layer 2 GEMM: warp w -> channels 32w..32w+31 (channel-packed) ----
    {
        const int cwb = 32 * w;
        u64 acc2[8][2];
#pragma unroll
        for (int nn = 0; nn < 8; nn++) { acc2[nn][0] = 0; acc2[nn][1] = 0; }

#pragma unroll 2
        for (int f0 = 0; f0 < FH; f0 += 4) {
            ulonglong2 wv[4];
#pragma unroll
            for (int k = 0; k < 4; k++)
                wv[k] = *(const ulonglong2*)(W2 + (f0 + k) * FH + cwb + 4 * cq);
#pragma unroll
            for (int nn = 0; nn < 8; nn++) {
                float4 hv = *(const float4*)&hs[4 * nn + ngrp][f0];   // 4 consec rows: 1 wf
                u64 d0 = dup2(hv.x), d1 = dup2(hv.y), d2 = dup2(hv.z), d3 = dup2(hv.w);
                fma2(acc2[nn][0], d0, wv[0].x); fma2(acc2[nn][1], d0, wv[0].y);
                fma2(acc2[nn][0], d1, wv[1].x); fma2(acc2[nn][1], d1, wv[1].y);
                fma2(acc2[nn][0], d2, wv[2].x); fma2(acc2[nn][1], d2, wv[2].y);
                fma2(acc2[nn][0], d3, wv[3].x); fma2(acc2[nn][1], d3, wv[3].y);
            }
        }
        __syncthreads();   // all reads of hs complete before overwrite
#pragma unroll
        for (int nn = 0; nn < 8; nn++) {
            ulonglong2 o; o.x = acc2[nn][0]; o.y = acc2[nn][1];
            *(ulonglong2*)&hs[4 * nn + ngrp][cwb + 4 * cq] = o;
        }
    }
    __syncthreads();
    gat_attention32(hs, as2, ad2, b2, s_src, s_dst, alphas[w], t);

    // ---- layer 3 GEMM: warp w -> nodes 8w..8w+7 (channel-packed) ----
    {
        u64 acc2[2][2];
        acc2[0][0] = acc2[0][1] = acc2[1][0] = acc2[1][1] = 0;

#pragma unroll 4
        for (int f0 = 0; f0 < FH; f0 += 4) {
            ulonglong2 wv[4];
#pragma unroll
            for (int k = 0; k < 4; k++)
                wv[k] = *(const ulonglong2*)(W3p_g + (f0 + k) * 32 + 4 * cq);
#pragma unroll
            for (int s = 0; s < 2; s++) {
                float4 hv = *(const float4*)&hs[8 * w + 4 * s + ngrp][f0];
                u64 d0 = dup2(hv.x), d1 = dup2(hv.y), d2 = dup2(hv.z), d3 = dup2(hv.w);
                fma2(acc2[s][0], d0, wv[0].x); fma2(acc2[s][1], d0, wv[0].y);
                fma2(acc2[s][0], d1, wv[1].x); fma2(acc2[s][1], d1, wv[1].y);
                fma2(acc2[s][0], d2, wv[2].x); fma2(acc2[s][1], d2, wv[2].y);
                fma2(acc2[s][0], d3, wv[3].x); fma2(acc2[s][1], d3, wv[3].y);
            }
        }
#pragma unroll
        for (int s = 0; s < 2; s++) {
            ulonglong2 o; o.x = acc2[s][0]; o.y = acc2[s][1];
            *(ulonglong2*)&hs[8 * w + 4 * s + ngrp][4 * cq] = o;
        }
    }
    __syncthreads();
    gat_attention6(hs, as3, ad3, b3, s_src, s_dst, t);

    // ---- final: mean over nodes commutes with linear (padded layout) ----
    if (t < F3) {
        int head = t / 6, d = t - head * 6;
        float s = 0.f;
#pragma unroll
        for (int n = 0; n < NCOL; n++) s += hs[n][head * 8 + d];
        cs[t] = s * (1.f / 32.f);
    }
    __syncthreads();
    if (t < 64) {
        float acc = lb[t];
#pragma unroll
        for (int k = 0; k < F3; k++) acc = fmaf(cs[k], lw[k * 64 + t], acc);
        out[(size_t)g * 64 + t] = acc;
    }
}

extern "C" void kernel_launch(void* const* d_in, const int* in_sizes, int n_in,
                              void* d_out, int out_size)
{
    const float* xs  = (const float*)d_in[0];
    const float* pe  = (const float*)d_in[1];
    const float* W1  = (const float*)d_in[2];
    const float* as1 = (const float*)d_in[3];
    const float* ad1 = (const float*)d_in[4];
    const float* b1  = (const float*)d_in[5];
    const float* W2  = (const float*)d_in[6];
    const float* as2 = (const float*)d_in[7];
    const float* ad2 = (const float*)d_in[8];
    const float* b2  = (const float*)d_in[9];
    const float* W3  = (const float*)d_in[10];
    const float* as3 = (const float*)d_in[11];
    const float* ad3 = (const float*)d_in[12];
    const float* b3  = (const float*)d_in[13];
    const float* lw  = (const float*)d_in[14];
    const float* lb  = (const float*)d_in[15];
    float* out = (float*)d_out;

    int B = in_sizes[1] / (32 * 15);
    int R = in_sizes[0] / (B * 32);
    int G = B * R;

    pad_w3_kernel<<<32, 128>>>(W3);
    gat_fused_kernel<<<G, THREADS>>>(xs, pe, W1, as1, ad1, b1,
                                     W2, as2, ad2, b2,
                                     as3, ad3, b3,
                                     lw, lb, out, R);
}